// round 1
// baseline (speedup 1.0000x reference)
#include <cuda_runtime.h>
#include <cstdint>

typedef unsigned long long ull;

#define T_ROLL 32
#define HDIM   1024
#define IDIM   1024
#define GDIM   4096          // 4*H
#define NTRAJ  2048
#define NROWS  (NTRAJ * T_ROLL)   // 65536

// Scratch (static device globals: allocation-free, allowed by harness rules)
__device__ float g_xgates[(size_t)NROWS * GDIM];  // 1 GiB: x @ Wih^T + b_ih + b_hh for all rows
__device__ float g_gates[(size_t)NTRAJ * GDIM];   // 32 MB: per-step gate preactivations
__device__ float g_h[NTRAJ * HDIM];
__device__ float g_c[NTRAJ * HDIM];

__device__ __forceinline__ void fma2(ull &c, ull a, ull b) {
    // packed fp32x2 FMA (sm_100+); ptxas will not auto-fuse this from C++
    asm("fma.rn.f32x2 %0, %1, %2, %0;" : "+l"(c) : "l"(a), "l"(b));
}

__device__ __forceinline__ float sigmoidf_(float x) { return 1.0f / (1.0f + expf(-x)); }

// C[m,n] = sum_k (keep_m * A[m,k]) * B[n,k]  (+ bias0[n]+bias1[n])  (+ addend[m*addStride + n])
// A: M x K row-major, B: N x K row-major (both K-contiguous: inner-product GEMM)
// BM=BN=128, BK=8, 256 threads, 8x8 per thread, double-buffered smem,
// A stored in smem pre-duplicated as {a,a} float2 so the inner loop is pure FFMA2.
__global__ __launch_bounds__(256, 2)
void gemm_kernel(const float* __restrict__ A, const float* __restrict__ B,
                 float* __restrict__ C, int M, int N, int K,
                 const float* __restrict__ bias0, const float* __restrict__ bias1,
                 const float* __restrict__ addend, long long addStride,
                 const float* __restrict__ dones, int t)
{
    __shared__ __align__(16) float2 As[2][8][128];
    __shared__ __align__(16) float  Bs[2][8][128];

    const int tid = threadIdx.x;
    const int row0 = blockIdx.y * 128;
    const int col0 = blockIdx.x * 128;

    const int lr = tid >> 1;            // 0..127 row within tile (for loads)
    const int lk = (tid & 1) << 2;      // 0 or 4 (k sub-group)

    const float* Aptr = A + (size_t)(row0 + lr) * K + lk;
    const float* Bptr = B + (size_t)(col0 + lr) * K + lk;

    float keep = 1.0f;
    if (dones != nullptr && t > 0)
        keep = 1.0f - dones[(row0 + lr) * T_ROLL + t - 1];

    const int tx = tid & 15, ty = tid >> 4;
    const int mbase = ty * 8, nbase = tx * 8;

    ull c2[8][4];
    #pragma unroll
    for (int i = 0; i < 8; i++)
        #pragma unroll
        for (int j = 0; j < 4; j++) c2[i][j] = 0ull;   // {0.f, 0.f}

    // ---- load tile 0 ----
    {
        float4 av = *(const float4*)(Aptr);
        float4 bv = *(const float4*)(Bptr);
        av.x *= keep; av.y *= keep; av.z *= keep; av.w *= keep;
        As[0][lk + 0][lr] = make_float2(av.x, av.x);
        As[0][lk + 1][lr] = make_float2(av.y, av.y);
        As[0][lk + 2][lr] = make_float2(av.z, av.z);
        As[0][lk + 3][lr] = make_float2(av.w, av.w);
        Bs[0][lk + 0][lr] = bv.x;
        Bs[0][lk + 1][lr] = bv.y;
        Bs[0][lk + 2][lr] = bv.z;
        Bs[0][lk + 3][lr] = bv.w;
    }
    __syncthreads();

    const int nk = K >> 3;
    for (int kt = 0; kt < nk; kt++) {
        const int buf = kt & 1;
        float4 av2, bv2;
        const bool pf = (kt + 1 < nk);
        if (pf) {
            av2 = *(const float4*)(Aptr + (kt + 1) * 8);
            bv2 = *(const float4*)(Bptr + (kt + 1) * 8);
        }
        #pragma unroll
        for (int k = 0; k < 8; k++) {
            ull a2[8], b2[4];
            *(float4*)(&a2[0]) = *(const float4*)(&As[buf][k][mbase + 0]);
            *(float4*)(&a2[2]) = *(const float4*)(&As[buf][k][mbase + 2]);
            *(float4*)(&a2[4]) = *(const float4*)(&As[buf][k][mbase + 4]);
            *(float4*)(&a2[6]) = *(const float4*)(&As[buf][k][mbase + 6]);
            *(float4*)(&b2[0]) = *(const float4*)(&Bs[buf][k][nbase + 0]);
            *(float4*)(&b2[2]) = *(const float4*)(&Bs[buf][k][nbase + 4]);
            #pragma unroll
            for (int i = 0; i < 8; i++)
                #pragma unroll
                for (int j = 0; j < 4; j++)
                    fma2(c2[i][j], a2[i], b2[j]);
        }
        if (pf) {
            const int nb = buf ^ 1;
            av2.x *= keep; av2.y *= keep; av2.z *= keep; av2.w *= keep;
            As[nb][lk + 0][lr] = make_float2(av2.x, av2.x);
            As[nb][lk + 1][lr] = make_float2(av2.y, av2.y);
            As[nb][lk + 2][lr] = make_float2(av2.z, av2.z);
            As[nb][lk + 3][lr] = make_float2(av2.w, av2.w);
            Bs[nb][lk + 0][lr] = bv2.x;
            Bs[nb][lk + 1][lr] = bv2.y;
            Bs[nb][lk + 2][lr] = bv2.z;
            Bs[nb][lk + 3][lr] = bv2.w;
        }
        __syncthreads();
    }

    // ---- epilogue ----
    const int n0 = col0 + nbase;
    #pragma unroll
    for (int i = 0; i < 8; i++) {
        const int m = row0 + mbase + i;
        float v[8];
        #pragma unroll
        for (int j = 0; j < 4; j++) {
            ull p = c2[i][j];
            v[2 * j]     = __uint_as_float((unsigned)(p & 0xffffffffu));
            v[2 * j + 1] = __uint_as_float((unsigned)(p >> 32));
        }
        if (bias0 != nullptr) {
            #pragma unroll
            for (int j = 0; j < 8; j++) v[j] += bias0[n0 + j] + bias1[n0 + j];
        }
        if (addend != nullptr) {
            const float* ap = addend + (size_t)m * addStride + n0;
            #pragma unroll
            for (int j = 0; j < 8; j++) v[j] += ap[j];
        }
        float4* cp = (float4*)(C + (size_t)m * N + n0);
        cp[0] = make_float4(v[0], v[1], v[2], v[3]);
        cp[1] = make_float4(v[4], v[5], v[6], v[7]);
    }
}

__global__ void init_states(const float* __restrict__ rnn)
{
    int idx = blockIdx.x * blockDim.x + threadIdx.x;
    int b = idx >> 10, j = idx & 1023;
    g_h[idx] = rnn[b * 2 * HDIM + j];
    g_c[idx] = rnn[b * 2 * HDIM + HDIM + j];
}

__global__ void lstm_elem(const float* __restrict__ dones, float* __restrict__ xout, int t)
{
    int idx = blockIdx.x * blockDim.x + threadIdx.x;
    int b = idx >> 10, j = idx & 1023;
    float keep = (t == 0) ? 1.0f : (1.0f - dones[b * T_ROLL + t - 1]);
    const float* g = g_gates + (size_t)b * GDIM;
    float ig = sigmoidf_(g[j]);
    float fg = sigmoidf_(g[HDIM + j]);
    float gg = tanhf(g[2 * HDIM + j]);
    float og = sigmoidf_(g[3 * HDIM + j]);
    float c = g_c[idx] * keep;
    c = fg * c + ig * gg;
    float h = og * tanhf(c);
    g_c[idx] = c;
    g_h[idx] = h;
    xout[((size_t)b * T_ROLL + t) * HDIM + j] = h;
}

__global__ void write_states(float* __restrict__ out)
{
    int idx = blockIdx.x * blockDim.x + threadIdx.x;
    int b = idx >> 10, j = idx & 1023;
    out[b * 2 * HDIM + j] = g_h[idx];
    out[b * 2 * HDIM + HDIM + j] = g_c[idx];
}

extern "C" void kernel_launch(void* const* d_in, const int* in_sizes, int n_in,
                              void* d_out, int out_size)
{
    const float* head  = (const float*)d_in[0];   // (B*T, I)
    const float* rnn   = (const float*)d_in[1];   // (B, 2H)
    const float* dones = (const float*)d_in[2];   // (B*T,)
    const float* wih   = (const float*)d_in[3];   // (4H, I)
    const float* whh   = (const float*)d_in[4];   // (4H, H)
    const float* bih   = (const float*)d_in[5];   // (4H,)
    const float* bhh   = (const float*)d_in[6];   // (4H,)
    float* out = (float*)d_out;

    float *xg = nullptr, *gt = nullptr, *hp = nullptr;
    cudaGetSymbolAddress((void**)&xg, g_xgates);
    cudaGetSymbolAddress((void**)&gt, g_gates);
    cudaGetSymbolAddress((void**)&hp, g_h);

    init_states<<<(NTRAJ * HDIM) / 256, 256>>>(rnn);

    // x_gates = X @ Wih^T + b_ih + b_hh  (65536 x 4096)
    gemm_kernel<<<dim3(GDIM / 128, NROWS / 128), 256>>>(
        head, wih, xg, NROWS, GDIM, IDIM, bih, bhh, nullptr, 0, nullptr, 0);

    for (int t = 0; t < T_ROLL; t++) {
        // gates = (keep * h) @ Whh^T + x_gates[t]   (2048 x 4096)
        gemm_kernel<<<dim3(GDIM / 128, NTRAJ / 128), 256>>>(
            hp, whh, gt, NTRAJ, GDIM, HDIM,
            nullptr, nullptr,
            xg + (size_t)t * GDIM, (long long)T_ROLL * GDIM,
            dones, t);
        lstm_elem<<<(NTRAJ * HDIM) / 256, 256>>>(dones, out, t);
    }

    write_states<<<(NTRAJ * HDIM) / 256, 256>>>(out + (size_t)NROWS * HDIM);
}

// round 4
// speedup vs baseline: 2.9651x; 2.9651x over previous
#include <cuda_runtime.h>
#include <cuda_bf16.h>
#include <cstdint>

#define T_ROLL 32
#define HDIM   1024
#define GDIM   4096
#define NTRAJ  2048
#define NROWS  65536
#define KDIM   1024

#define STAGES 3
#define RB     80                 // smem row stride bytes (32 bf16 + 8 pad)
#define OP_BYTES (128 * RB)       // 10240 per operand tile
#define OFF_AH 0
#define OFF_AL (OP_BYTES)
#define OFF_BH (2 * OP_BYTES)
#define OFF_BL (3 * OP_BYTES)
#define STAGE_BYTES (4 * OP_BYTES)          // 40960
#define SMEM_TOTAL (STAGES * STAGE_BYTES)   // 122880
#define NC32   (KDIM / 32)                  // 32 k-chunks

// ---------------- scratch --------------------------------------------------
__device__ float g_xgates[(size_t)NROWS * GDIM];          // 1 GiB
__device__ float g_gates[(size_t)NTRAJ * GDIM];
__device__ float g_c[NTRAJ * HDIM];
__device__ __nv_bfloat16 g_hhi[NTRAJ * HDIM];
__device__ __nv_bfloat16 g_hlo[NTRAJ * HDIM];
__device__ __nv_bfloat16 g_xhi[(size_t)NROWS * KDIM];
__device__ __nv_bfloat16 g_xlo[(size_t)NROWS * KDIM];
__device__ __nv_bfloat16 g_wihhi[(size_t)GDIM * KDIM];
__device__ __nv_bfloat16 g_wihlo[(size_t)GDIM * KDIM];
__device__ __nv_bfloat16 g_whhhi[(size_t)GDIM * KDIM];
__device__ __nv_bfloat16 g_whhlo[(size_t)GDIM * KDIM];
__device__ float g_bias[GDIM];

// ---------------- PTX helpers ---------------------------------------------
__device__ __forceinline__ uint32_t smem_u32(const void* p) {
    uint32_t a;
    asm("{ .reg .u64 t; cvta.to.shared.u64 t, %1; cvt.u32.u64 %0, t; }" : "=r"(a) : "l"(p));
    return a;
}
__device__ __forceinline__ void cp16(uint32_t dst, const void* src) {
    asm volatile("cp.async.cg.shared.global [%0], [%1], 16;" :: "r"(dst), "l"(src));
}
__device__ __forceinline__ void cp_commit() {
    asm volatile("cp.async.commit_group;" ::: "memory");
}
__device__ __forceinline__ void ldm4(uint32_t* r, uint32_t addr) {
    asm volatile("ldmatrix.sync.aligned.m8n8.x4.shared.b16 {%0,%1,%2,%3}, [%4];"
        : "=r"(r[0]), "=r"(r[1]), "=r"(r[2]), "=r"(r[3]) : "r"(addr));
}
__device__ __forceinline__ void mma16816(float* d, const uint32_t* a, const uint32_t* b) {
    asm volatile("mma.sync.aligned.m16n8k16.row.col.f32.bf16.bf16.f32 "
        "{%0,%1,%2,%3}, {%4,%5,%6,%7}, {%8,%9}, {%0,%1,%2,%3};"
        : "+f"(d[0]), "+f"(d[1]), "+f"(d[2]), "+f"(d[3])
        : "r"(a[0]), "r"(a[1]), "r"(a[2]), "r"(a[3]), "r"(b[0]), "r"(b[1]));
}

// ---------------- HMMA split GEMM ------------------------------------------
// C[m,n] = sum_k A[m,k]*B[n,k] (+bias[n]) (+addend[m*addStride+n])
// A,B bf16 hi/lo pre-split; D = Ahi*Bhi + Ahi*Blo + Alo*Bhi, fp32 accum.
// Tile 128x128, BK=32, 8 warps of 32x64, ldmatrix + cp.async 3-stage.
__global__ __launch_bounds__(256, 1)
void gemm_hmma(const __nv_bfloat16* __restrict__ Ahi, const __nv_bfloat16* __restrict__ Alo,
               const __nv_bfloat16* __restrict__ Bhi, const __nv_bfloat16* __restrict__ Blo,
               float* __restrict__ C,
               const float* __restrict__ bias,
               const float* __restrict__ addend, long long addStride)
{
    extern __shared__ char smem[];
    const uint32_t sbase = smem_u32(smem);
    const int tid = threadIdx.x;
    const int wid = tid >> 5, lane = tid & 31;
    const int wr = wid & 3, wc = wid >> 2;       // warp: rows wr*32, cols wc*64
    const int row0 = blockIdx.y * 128;
    const int col0 = blockIdx.x * 128;

    // per-thread copy slots (2 x 16B per operand per stage)
    int cr[2], cq[2];
    {
        int v0 = tid, v1 = tid + 256;
        cr[0] = v0 >> 2; cq[0] = v0 & 3;
        cr[1] = v1 >> 2; cq[1] = v1 & 3;
    }

    // ldmatrix lane offsets
    const int g = lane >> 3, r = lane & 7;
    const uint32_t a_off = (uint32_t)((wr * 32 + (g & 1) * 8 + r) * RB + (g >> 1) * 16);
    const uint32_t b_off = (uint32_t)((wc * 64 + (g >> 1) * 8 + r) * RB + (g & 1) * 16);

    float acc[2][8][4];
    #pragma unroll
    for (int mi = 0; mi < 2; mi++)
        #pragma unroll
        for (int ni = 0; ni < 8; ni++)
            #pragma unroll
            for (int q = 0; q < 4; q++) acc[mi][ni][q] = 0.0f;

    // ---- issue one k-chunk's 4 operand tiles into a stage ----
    auto issue = [&](int c) {
        const uint32_t sb = sbase + (uint32_t)(c % STAGES) * STAGE_BYTES;
        const int kc = c * 32;
        #pragma unroll
        for (int i = 0; i < 2; i++) {
            const int row = cr[i], q = cq[i];
            const uint32_t doff = (uint32_t)(row * RB + q * 16);
            const size_t ga = (size_t)(row0 + row) * KDIM + kc + q * 8;
            const size_t gb = (size_t)(col0 + row) * KDIM + kc + q * 8;
            cp16(sb + OFF_AH + doff, Ahi + ga);
            cp16(sb + OFF_AL + doff, Alo + ga);
            cp16(sb + OFF_BH + doff, Bhi + gb);
            cp16(sb + OFF_BL + doff, Blo + gb);
        }
    };

    #pragma unroll
    for (int s = 0; s < STAGES - 1; s++) { issue(s); cp_commit(); }

    for (int c = 0; c < NC32; c++) {
        asm volatile("cp.async.wait_group %0;" :: "n"(STAGES - 2));
        __syncthreads();

        const uint32_t sb = sbase + (uint32_t)(c % STAGES) * STAGE_BYTES;
        #pragma unroll
        for (int kk = 0; kk < 2; kk++) {
            uint32_t ah[2][4], al[2][4];
            #pragma unroll
            for (int mi = 0; mi < 2; mi++) {
                ldm4(ah[mi], sb + OFF_AH + a_off + mi * 16 * RB + kk * 32);
                ldm4(al[mi], sb + OFF_AL + a_off + mi * 16 * RB + kk * 32);
            }
            uint32_t bh[8][2], bl[8][2];
            #pragma unroll
            for (int nj = 0; nj < 4; nj++) {
                uint32_t t4[4];
                ldm4(t4, sb + OFF_BH + b_off + nj * 16 * RB + kk * 32);
                bh[2 * nj][0] = t4[0]; bh[2 * nj][1] = t4[1];
                bh[2 * nj + 1][0] = t4[2]; bh[2 * nj + 1][1] = t4[3];
                ldm4(t4, sb + OFF_BL + b_off + nj * 16 * RB + kk * 32);
                bl[2 * nj][0] = t4[0]; bl[2 * nj][1] = t4[1];
                bl[2 * nj + 1][0] = t4[2]; bl[2 * nj + 1][1] = t4[3];
            }
            #pragma unroll
            for (int mi = 0; mi < 2; mi++)
                #pragma unroll
                for (int ni = 0; ni < 8; ni++) {
                    mma16816(acc[mi][ni], ah[mi], bh[ni]);
                    mma16816(acc[mi][ni], ah[mi], bl[ni]);
                    mma16816(acc[mi][ni], al[mi], bh[ni]);
                }
        }

        const int p = c + STAGES - 1;
        if (p < NC32) issue(p);
        cp_commit();
    }

    // ---- epilogue ----
    const int qr = lane >> 2, qc = (lane & 3) * 2;
    #pragma unroll
    for (int mi = 0; mi < 2; mi++) {
        const int m0 = row0 + wr * 32 + mi * 16 + qr;
        #pragma unroll
        for (int ni = 0; ni < 8; ni++) {
            const int col = col0 + wc * 64 + ni * 8 + qc;
            float b0 = 0.0f, b1 = 0.0f;
            if (bias != nullptr) { b0 = bias[col]; b1 = bias[col + 1]; }
            float a00 = 0.f, a01 = 0.f, a10 = 0.f, a11 = 0.f;
            if (addend != nullptr) {
                const float* p0 = addend + (size_t)m0 * addStride + col;
                const float* p1 = addend + (size_t)(m0 + 8) * addStride + col;
                a00 = p0[0]; a01 = p0[1]; a10 = p1[0]; a11 = p1[1];
            }
            *(float2*)(C + (size_t)m0 * GDIM + col) =
                make_float2(acc[mi][ni][0] + b0 + a00, acc[mi][ni][1] + b1 + a01);
            *(float2*)(C + (size_t)(m0 + 8) * GDIM + col) =
                make_float2(acc[mi][ni][2] + b0 + a10, acc[mi][ni][3] + b1 + a11);
        }
    }
}

// ---------------- elementwise kernels --------------------------------------
__device__ __forceinline__ float sigmoidf_(float x) { return 1.0f / (1.0f + expf(-x)); }

__global__ void split_bf16(const float* __restrict__ in,
                           __nv_bfloat16* __restrict__ hi, __nv_bfloat16* __restrict__ lo)
{
    int idx = (blockIdx.x * blockDim.x + threadIdx.x) * 4;
    float4 v = *(const float4*)(in + idx);
    __nv_bfloat16 h0 = __float2bfloat16(v.x), h1 = __float2bfloat16(v.y);
    __nv_bfloat16 h2 = __float2bfloat16(v.z), h3 = __float2bfloat16(v.w);
    __nv_bfloat16 l0 = __float2bfloat16(v.x - __bfloat162float(h0));
    __nv_bfloat16 l1 = __float2bfloat16(v.y - __bfloat162float(h1));
    __nv_bfloat16 l2 = __float2bfloat16(v.z - __bfloat162float(h2));
    __nv_bfloat16 l3 = __float2bfloat16(v.w - __bfloat162float(h3));
    __nv_bfloat162* hp = (__nv_bfloat162*)(hi + idx);
    __nv_bfloat162* lp = (__nv_bfloat162*)(lo + idx);
    hp[0] = __nv_bfloat162(h0, h1); hp[1] = __nv_bfloat162(h2, h3);
    lp[0] = __nv_bfloat162(l0, l1); lp[1] = __nv_bfloat162(l2, l3);
}

__global__ void bias_combine(const float* __restrict__ a, const float* __restrict__ b)
{
    int i = blockIdx.x * blockDim.x + threadIdx.x;
    g_bias[i] = a[i] + b[i];
}

__global__ void init_states(const float* __restrict__ rnn)
{
    int idx = blockIdx.x * blockDim.x + threadIdx.x;
    int b = idx >> 10, j = idx & 1023;
    float h = rnn[b * 2 * HDIM + j];
    g_c[idx] = rnn[b * 2 * HDIM + HDIM + j];
    __nv_bfloat16 hh = __float2bfloat16(h);
    g_hhi[idx] = hh;
    g_hlo[idx] = __float2bfloat16(h - __bfloat162float(hh));
}

// writes xout = h (unmasked); writes h hi/lo PRE-MASKED for the next step's GEMM
__global__ void lstm_elem(const float* __restrict__ dones, float* __restrict__ xout, int t)
{
    int idx = blockIdx.x * blockDim.x + threadIdx.x;
    int b = idx >> 10, j = idx & 1023;
    float keep = (t == 0) ? 1.0f : (1.0f - dones[b * T_ROLL + t - 1]);
    const float* g = g_gates + (size_t)b * GDIM;
    float ig = sigmoidf_(g[j]);
    float fg = sigmoidf_(g[HDIM + j]);
    float gg = tanhf(g[2 * HDIM + j]);
    float og = sigmoidf_(g[3 * HDIM + j]);
    float c = g_c[idx] * keep;
    c = fg * c + ig * gg;
    float h = og * tanhf(c);
    g_c[idx] = c;
    float hm = (dones[b * T_ROLL + t] != 0.0f) ? 0.0f : h;   // mask for step t+1
    __nv_bfloat16 hh = __float2bfloat16(hm);
    g_hhi[idx] = hh;
    g_hlo[idx] = __float2bfloat16(hm - __bfloat162float(hh));
    xout[((size_t)b * T_ROLL + t) * HDIM + j] = h;
}

__global__ void write_states(const float* __restrict__ xout, float* __restrict__ out)
{
    int idx = blockIdx.x * blockDim.x + threadIdx.x;
    int b = idx >> 10, j = idx & 1023;
    out[b * 2 * HDIM + j] = xout[((size_t)b * T_ROLL + T_ROLL - 1) * HDIM + j];
    out[b * 2 * HDIM + HDIM + j] = g_c[idx];
}

// ---------------- launch ---------------------------------------------------
extern "C" void kernel_launch(void* const* d_in, const int* in_sizes, int n_in,
                              void* d_out, int out_size)
{
    const float* head  = (const float*)d_in[0];
    const float* rnn   = (const float*)d_in[1];
    const float* dones = (const float*)d_in[2];
    const float* wih   = (const float*)d_in[3];
    const float* whh   = (const float*)d_in[4];
    const float* bih   = (const float*)d_in[5];
    const float* bhh   = (const float*)d_in[6];
    float* out = (float*)d_out;

    static bool attr_set = false;
    if (!attr_set) {
        cudaFuncSetAttribute(gemm_hmma, cudaFuncAttributeMaxDynamicSharedMemorySize, SMEM_TOTAL);
        attr_set = true;
    }

    float *xg, *gt, *bptr;
    __nv_bfloat16 *xhi, *xlo, *wihhi, *wihlo, *whhhi, *whhlo, *hhi, *hlo;
    cudaGetSymbolAddress((void**)&xg, g_xgates);
    cudaGetSymbolAddress((void**)&gt, g_gates);
    cudaGetSymbolAddress((void**)&bptr, g_bias);
    cudaGetSymbolAddress((void**)&xhi, g_xhi);
    cudaGetSymbolAddress((void**)&xlo, g_xlo);
    cudaGetSymbolAddress((void**)&wihhi, g_wihhi);
    cudaGetSymbolAddress((void**)&wihlo, g_wihlo);
    cudaGetSymbolAddress((void**)&whhhi, g_whhhi);
    cudaGetSymbolAddress((void**)&whhlo, g_whhlo);
    cudaGetSymbolAddress((void**)&hhi, g_hhi);
    cudaGetSymbolAddress((void**)&hlo, g_hlo);

    split_bf16<<<(size_t)NROWS * KDIM / 1024, 256>>>(head, xhi, xlo);
    split_bf16<<<(size_t)GDIM * KDIM / 1024, 256>>>(wih, wihhi, wihlo);
    split_bf16<<<(size_t)GDIM * KDIM / 1024, 256>>>(whh, whhhi, whhlo);
    bias_combine<<<GDIM / 256, 256>>>(bih, bhh);
    init_states<<<(NTRAJ * HDIM) / 256, 256>>>(rnn);

    // x_gates = X @ Wih^T + (b_ih + b_hh)   (65536 x 4096)
    gemm_hmma<<<dim3(GDIM / 128, NROWS / 128), 256, SMEM_TOTAL>>>(
        xhi, xlo, wihhi, wihlo, xg, bptr, nullptr, 0);

    for (int t = 0; t < T_ROLL; t++) {
        // gates = (masked h) @ Whh^T + x_gates[t]   (2048 x 4096)
        gemm_hmma<<<dim3(GDIM / 128, NTRAJ / 128), 256, SMEM_TOTAL>>>(
            hhi, hlo, whhhi, whhlo, gt, nullptr,
            xg + (size_t)t * GDIM, (long long)T_ROLL * GDIM);
        lstm_elem<<<(NTRAJ * HDIM) / 256, 256>>>(dones, out, t);
    }

    write_states<<<(NTRAJ * HDIM) / 256, 256>>>(out, out + (size_t)NROWS * HDIM);
}